// round 14
// baseline (speedup 1.0000x reference)
#include <cuda_runtime.h>
#include <cuda_bf16.h>
#include <cstdint>
#include <cstddef>

// ---------------- problem constants ----------------
#define NROWS 8192
#define NC    128
#define NLAB  1024
#define STRIDE 136   // smem row stride in bf16 elements (padding kills ldmatrix conflicts)

// fp32 normalized features (row-major) for exact positive-pair math
__device__ float g_f1n[(size_t)NROWS * NC];
__device__ float g_f2n[(size_t)NROWS * NC];
// bf16 normalized features (row-major) for tensor-core GEMM
__device__ __nv_bfloat16 g_f1b[(size_t)NROWS * NC];
__device__ __nv_bfloat16 g_f2b[(size_t)NROWS * NC];

__device__ int   g_hist[NLAB];
__device__ int   g_labOff[NLAB + 1];
__device__ int   g_labCur[NLAB];
__device__ int   g_labRows[NROWS];

__device__ float g_lp[NROWS];      // logit_pos per row (exact fp32)
__device__ float g_ln[NROWS];      // logit_neg per row (accumulated by GEMM epilogue)
__device__ float g_rt[NROWS];      // row_target
__device__ float g_possim;         // sum of clamped sim over positives
__device__ float g_psum;           // pos.sum() = sum h^2
__device__ float g_t;
__device__ float g_lossacc;
__device__ int   g_ctr1;           // last-block counter for k_pos
__device__ int   g_ctr2;           // last-block counter for k_loss

// hyperparameters
#define C_COSM      0.8775825618903728f
#define C_SINM      0.4794255386042030f
#define C_THRESHOLD (-0.8775825618903728f)
#define C_MM        0.2397127693021015f
#define C_INVT      (1.0f / 0.07f)
#define C_K2        20.6099291555f   // (1/0.07) * log2(e)  -> for ex2.approx
#define C_ALPHA     0.1f
#define C_EPS       1e-12f

// MUFU.EX2 directly (exp(x/T) == ex2(x * C_K2)); saves the FMUL __expf would add
__device__ __forceinline__ float ex2_approx(float x) {
    float r;
    asm("ex2.approx.f32 %0, %1;" : "=f"(r) : "f"(x));
    return r;
}

// ---------------- init (zero everything that gets accumulated) ----------------
__global__ void k_init() {
    int i = blockIdx.x * blockDim.x + threadIdx.x;
    if (i < NROWS) g_ln[i] = 0.0f;
    if (i < NLAB)  g_hist[i] = 0;
    if (i == 0) { g_possim = 0.0f; g_lossacc = 0.0f; g_ctr1 = 0; g_ctr2 = 0; }
}

// ---------------- fused: row-normalize (f1 AND f2) + histogram ----------------
// 16384 warp-rows: [0,8192) -> f1, [8192,16384) -> f2
__global__ void k_normhist(const float* __restrict__ f1, const float* __restrict__ f2,
                           const int* __restrict__ labels) {
    int gw   = (blockIdx.x * blockDim.x + threadIdx.x) >> 5;
    int lane = threadIdx.x & 31;
    int which = gw >= NROWS;
    int row = which ? gw - NROWS : gw;
    const float* in = which ? f2 : f1;
    float4 v = reinterpret_cast<const float4*>(in)[row * 32 + lane];
    float ss = v.x * v.x + v.y * v.y + v.z * v.z + v.w * v.w;
    #pragma unroll
    for (int off = 16; off > 0; off >>= 1)
        ss += __shfl_xor_sync(0xffffffffu, ss, off);
    float inv = 1.0f / fmaxf(sqrtf(ss), C_EPS);
    float4 o = make_float4(v.x * inv, v.y * inv, v.z * inv, v.w * inv);
    float* outN = which ? g_f2n : g_f1n;
    __nv_bfloat16* outB = which ? g_f2b : g_f1b;
    reinterpret_cast<float4*>(outN)[row * 32 + lane] = o;
    __nv_bfloat162 p0 = __floats2bfloat162_rn(o.x, o.y);
    __nv_bfloat162 p1 = __floats2bfloat162_rn(o.z, o.w);
    reinterpret_cast<__nv_bfloat162*>(outB)[row * 64 + lane * 2]     = p0;
    reinterpret_cast<__nv_bfloat162*>(outB)[row * 64 + lane * 2 + 1] = p1;
    if (!which && lane == 0) atomicAdd(&g_hist[__ldg(&labels[row])], 1);
}

// ---------------- label offsets: two-level warp shuffle scan + pos.sum ----------------
__global__ void k_scan() {
    __shared__ int   wsum[32];
    __shared__ float fsum[32];
    int tid = threadIdx.x, lane = tid & 31, w = tid >> 5;
    int h = g_hist[tid];
    float hh = (float)h * (float)h;

    int v = h;
    #pragma unroll
    for (int off = 1; off < 32; off <<= 1) {
        int u = __shfl_up_sync(0xffffffffu, v, off);
        if (lane >= off) v += u;
    }
    #pragma unroll
    for (int off = 16; off > 0; off >>= 1)
        hh += __shfl_xor_sync(0xffffffffu, hh, off);
    if (lane == 31) wsum[w] = v;
    if (lane == 0)  fsum[w] = hh;
    __syncthreads();
    if (w == 0) {
        int s = wsum[lane];
        #pragma unroll
        for (int off = 1; off < 32; off <<= 1) {
            int u = __shfl_up_sync(0xffffffffu, s, off);
            if (lane >= off) s += u;
        }
        wsum[lane] = s;
        float f = fsum[lane];
        #pragma unroll
        for (int off = 16; off > 0; off >>= 1)
            f += __shfl_xor_sync(0xffffffffu, f, off);
        if (lane == 0) g_psum = f;
    }
    __syncthreads();
    int incl = v + (w > 0 ? wsum[w - 1] : 0);
    g_labOff[tid + 1] = incl;
    g_labCur[tid] = incl - h;
    if (tid == 0) g_labOff[0] = 0;
}

__global__ void k_scatter(const int* __restrict__ labels) {
    int i = blockIdx.x * blockDim.x + threadIdx.x;
    if (i < NROWS) {
        int p = atomicAdd(&g_labCur[labels[i]], 1);
        g_labRows[p] = i;
    }
}

// ---------------- positive pairs (exact fp32) + fused t (last block) ----------------
__global__ void k_pos(const int* __restrict__ labels) {
    __shared__ float bps[8];
    int row  = (blockIdx.x * blockDim.x + threadIdx.x) >> 5;
    int lane = threadIdx.x & 31;
    int wid  = threadIdx.x >> 5;
    int lab = __ldg(&labels[row]);
    int beg = g_labOff[lab], end = g_labOff[lab + 1];
    float4 a = reinterpret_cast<const float4*>(g_f1n)[row * 32 + lane];

    float possim = 0.0f, fpsum = 0.0f, lpsum = 0.0f;
    for (int p = beg; p < end; ++p) {
        int j = g_labRows[p];
        float4 b = reinterpret_cast<const float4*>(g_f2n)[j * 32 + lane];
        float d = a.x * b.x + a.y * b.y + a.z * b.z + a.w * b.w;
        #pragma unroll
        for (int off = 16; off > 0; off >>= 1)
            d += __shfl_xor_sync(0xffffffffu, d, off);
        float s = fminf(fmaxf(d, -1.0f), 1.0f);
        possim += s;
        float fp;
        if (s > C_THRESHOLD)
            fp = s * C_COSM - sqrtf(fmaxf(1.0f - s * s, 0.0f)) * C_SINM;
        else
            fp = s - C_MM;
        fpsum += fp;
        lpsum += __expf(fp * C_INVT);
    }
    if (lane == 0) {
        int cnt = end - beg;
        g_rt[row] = fpsum / (float)cnt;
        g_lp[row] = lpsum;
        bps[wid] = possim;
    }
    __syncthreads();
    if (threadIdx.x == 0) {
        float ps = 0.0f;
        #pragma unroll
        for (int i = 0; i < 8; ++i) ps += bps[i];
        atomicAdd(&g_possim, ps);
        __threadfence();
        int c = atomicAdd(&g_ctr1, 1);
        if (c == (int)gridDim.x - 1)
            g_t = C_ALPHA * (g_possim / g_psum);
    }
}

// ---------------- fused bf16 tensor-core GEMM + logit_neg epilogue ----------------
struct SmemT {
    __nv_bfloat16 As[128 * STRIDE];
    __nv_bfloat16 Bs[128 * STRIDE];
    int   labA[128];
    int   labB[128];
    float rtS[128];
    float lnpart[128];
};

__device__ __forceinline__ void ldsm_x4(uint32_t& r0, uint32_t& r1, uint32_t& r2, uint32_t& r3,
                                        uint32_t addr) {
    asm volatile("ldmatrix.sync.aligned.m8n8.x4.shared.b16 {%0,%1,%2,%3}, [%4];\n"
                 : "=r"(r0), "=r"(r1), "=r"(r2), "=r"(r3) : "r"(addr));
}
__device__ __forceinline__ void ldsm_x2(uint32_t& r0, uint32_t& r1, uint32_t addr) {
    asm volatile("ldmatrix.sync.aligned.m8n8.x2.shared.b16 {%0,%1}, [%2];\n"
                 : "=r"(r0), "=r"(r1) : "r"(addr));
}
__device__ __forceinline__ void mma16816(float* d, const uint32_t* a, const uint32_t* b) {
    asm volatile("mma.sync.aligned.m16n8k16.row.col.f32.bf16.bf16.f32 "
                 "{%0,%1,%2,%3}, {%4,%5,%6,%7}, {%8,%9}, {%0,%1,%2,%3};\n"
                 : "+f"(d[0]), "+f"(d[1]), "+f"(d[2]), "+f"(d[3])
                 : "r"(a[0]), "r"(a[1]), "r"(a[2]), "r"(a[3]), "r"(b[0]), "r"(b[1]));
}

__device__ __forceinline__ float neg_term(float v, int la, int lb, float rt, float t) {
    float s = fminf(fmaxf(v, -1.0f), 1.0f);
    if (la == lb) return 0.0f;                  // positives excluded from logit_neg
    float s3 = (s > rt) ? s * (t + s) : s;      // curricular hard-negative boost
    return ex2_approx(s3 * C_K2);               // exp(s3/T) via single fused constant
}

__global__ __launch_bounds__(256, 2) void k_main(const int* __restrict__ labels) {
    extern __shared__ char smraw[];
    SmemT& sm = *reinterpret_cast<SmemT*>(smraw);
    const int tid = threadIdx.x, lane = tid & 31, wid = tid >> 5;
    const int bx = blockIdx.x, by = blockIdx.y;

    // ---- load 128x128 bf16 tiles (full K at once) ----
    const uint4* ga = reinterpret_cast<const uint4*>(g_f1b + (size_t)by * 128 * NC);
    const uint4* gb = reinterpret_cast<const uint4*>(g_f2b + (size_t)bx * 128 * NC);
    #pragma unroll
    for (int it = 0; it < 8; ++it) {
        int r = it * 16 + (tid >> 4);
        int c = tid & 15;                       // 16B chunk = 8 bf16
        uint4 va = ga[r * 16 + c];
        uint4 vb = gb[r * 16 + c];
        *reinterpret_cast<uint4*>(sm.As + r * STRIDE + c * 8) = va;
        *reinterpret_cast<uint4*>(sm.Bs + r * STRIDE + c * 8) = vb;
    }
    if (tid < 128) {
        sm.labA[tid] = labels[by * 128 + tid];
        sm.labB[tid] = labels[bx * 128 + tid];
        sm.rtS[tid]  = g_rt[by * 128 + tid];
        sm.lnpart[tid] = 0.0f;
    }
    __syncthreads();

    const int wm = wid >> 2;      // 0..1  -> 64 rows
    const int wn = wid & 3;       // 0..3  -> 32 cols

    float acc[4][4][4];
    #pragma unroll
    for (int mi = 0; mi < 4; ++mi)
        #pragma unroll
        for (int ni = 0; ni < 4; ++ni)
            #pragma unroll
            for (int e = 0; e < 4; ++e) acc[mi][ni][e] = 0.0f;

    uint32_t aBase = (uint32_t)__cvta_generic_to_shared(sm.As);
    uint32_t bBase = (uint32_t)__cvta_generic_to_shared(sm.Bs);

    #pragma unroll
    for (int k16 = 0; k16 < 8; ++k16) {
        uint32_t af[4][4], bf[4][2];
        #pragma unroll
        for (int mi = 0; mi < 4; ++mi) {
            int row = wm * 64 + mi * 16 + (lane & 15);
            uint32_t addr = aBase + (uint32_t)(row * STRIDE + k16 * 16 + (lane >> 4) * 8) * 2u;
            ldsm_x4(af[mi][0], af[mi][1], af[mi][2], af[mi][3], addr);
        }
        #pragma unroll
        for (int ni = 0; ni < 4; ++ni) {
            int nrow = wn * 32 + ni * 8 + (lane & 7);
            uint32_t addr = bBase + (uint32_t)(nrow * STRIDE + k16 * 16 + ((lane >> 3) & 1) * 8) * 2u;
            ldsm_x2(bf[ni][0], bf[ni][1], addr);
        }
        #pragma unroll
        for (int mi = 0; mi < 4; ++mi)
            #pragma unroll
            for (int ni = 0; ni < 4; ++ni)
                mma16816(acc[mi][ni], af[mi], bf[ni]);
    }

    // ---- epilogue: logit_neg accumulation, no sim write-back ----
    const float t = g_t;
    int lbr[8];
    #pragma unroll
    for (int ni = 0; ni < 4; ++ni) {
        int c0 = wn * 32 + ni * 8 + 2 * (lane & 3);
        lbr[2 * ni]     = sm.labB[c0];
        lbr[2 * ni + 1] = sm.labB[c0 + 1];
    }
    #pragma unroll
    for (int mi = 0; mi < 4; ++mi) {
        int rl = wm * 64 + mi * 16 + (lane >> 2);
        int rh = rl + 8;
        float rtl = sm.rtS[rl], rth = sm.rtS[rh];
        int   lal = sm.labA[rl], lah = sm.labA[rh];
        float sl = 0.0f, shi = 0.0f;
        #pragma unroll
        for (int ni = 0; ni < 4; ++ni) {
            sl  += neg_term(acc[mi][ni][0], lal, lbr[2 * ni],     rtl, t);
            sl  += neg_term(acc[mi][ni][1], lal, lbr[2 * ni + 1], rtl, t);
            shi += neg_term(acc[mi][ni][2], lah, lbr[2 * ni],     rth, t);
            shi += neg_term(acc[mi][ni][3], lah, lbr[2 * ni + 1], rth, t);
        }
        sl  += __shfl_xor_sync(0xffffffffu, sl, 1);
        sl  += __shfl_xor_sync(0xffffffffu, sl, 2);
        shi += __shfl_xor_sync(0xffffffffu, shi, 1);
        shi += __shfl_xor_sync(0xffffffffu, shi, 2);
        if ((lane & 3) == 0) {
            atomicAdd(&sm.lnpart[rl], sl);
            atomicAdd(&sm.lnpart[rh], shi);
        }
    }
    __syncthreads();
    if (tid < 128) atomicAdd(&g_ln[by * 128 + tid], sm.lnpart[tid]);
}

// ---------------- final loss (fused: last block writes output) ----------------
__global__ void k_loss(float* __restrict__ out) {
    int i = blockIdx.x * blockDim.x + threadIdx.x;
    float lp = g_lp[i];
    float v = logf((lp + g_ln[i]) / lp);   // == -log(lp/(ln+lp))
    #pragma unroll
    for (int off = 16; off > 0; off >>= 1)
        v += __shfl_xor_sync(0xffffffffu, v, off);
    __shared__ float ws[8];
    int wid = threadIdx.x >> 5, lane = threadIdx.x & 31;
    if (lane == 0) ws[wid] = v;
    __syncthreads();
    if (threadIdx.x == 0) {
        float s = 0.0f;
        #pragma unroll
        for (int w = 0; w < 8; ++w) s += ws[w];
        atomicAdd(&g_lossacc, s);
        __threadfence();
        int c = atomicAdd(&g_ctr2, 1);
        if (c == (int)gridDim.x - 1)
            out[0] = g_lossacc * (1.0f / (float)NROWS);
    }
}

// ---------------- launch ----------------
extern "C" void kernel_launch(void* const* d_in, const int* in_sizes, int n_in,
                              void* d_out, int out_size) {
    const float* f1 = (const float*)d_in[0];
    const float* f2 = (const float*)d_in[1];
    const int* labels = (const int*)d_in[2];
    float* out = (float*)d_out;

    cudaFuncSetAttribute(k_main, cudaFuncAttributeMaxDynamicSharedMemorySize,
                         (int)sizeof(SmemT));

    k_init<<<(NROWS + 255) / 256, 256>>>();
    k_normhist<<<2 * NROWS / 8, 256>>>(f1, f2, labels);
    k_scan<<<1, NLAB>>>();
    k_scatter<<<(NROWS + 255) / 256, 256>>>(labels);
    k_pos<<<NROWS / 8, 256>>>(labels);

    dim3 grid(NROWS / 128, NROWS / 128);
    k_main<<<grid, 256, sizeof(SmemT)>>>(labels);

    k_loss<<<NROWS / 256, 256>>>(out);
}

// round 16
// speedup vs baseline: 1.0429x; 1.0429x over previous
#include <cuda_runtime.h>
#include <cuda_fp16.h>
#include <cuda_bf16.h>
#include <cstdint>
#include <cstddef>

// ---------------- problem constants ----------------
#define NROWS 8192
#define NC    128
#define NLAB  1024
#define STRIDE 136   // smem row stride in f16 elements (padding kills ldmatrix conflicts)

// fp32 normalized features (row-major) for exact positive-pair math
__device__ float g_f1n[(size_t)NROWS * NC];
__device__ float g_f2n[(size_t)NROWS * NC];
// f16 normalized features (row-major) for tensor-core GEMM
__device__ __half g_f1h[(size_t)NROWS * NC];
__device__ __half g_f2h[(size_t)NROWS * NC];

__device__ int   g_labOff[NLAB + 1];
__device__ int   g_labRows[NROWS];

__device__ float g_lp[NROWS];      // logit_pos per row (exact fp32)
__device__ float g_ln[NROWS];      // logit_neg per row (accumulated by GEMM epilogue)
__device__ float g_rt[NROWS];      // row_target
__device__ float g_possim;         // sum of clamped sim over positives
__device__ float g_psum;           // pos.sum() = sum h^2
__device__ float g_t;
__device__ float g_lossacc;
__device__ int   g_ctr1;           // last-block counter for k_pos
__device__ int   g_ctr2;           // last-block counter for k_loss

// hyperparameters
#define C_COSM      0.8775825618903728f
#define C_SINM      0.4794255386042030f
#define C_THRESHOLD (-0.8775825618903728f)
#define C_MM        0.2397127693021015f
#define C_INVT      (1.0f / 0.07f)
#define C_K2        20.6099291555f   // (1/0.07) * log2(e)  -> for ex2.approx
#define C_ALPHA     0.1f
#define C_EPS       1e-12f

// MUFU.EX2 directly (exp(x/T) == ex2(x * C_K2))
__device__ __forceinline__ float ex2_approx(float x) {
    float r;
    asm("ex2.approx.f32 %0, %1;" : "=f"(r) : "f"(x));
    return r;
}

// ---------------- fused: row-normalize (f1 AND f2) + zero g_ln ----------------
__global__ void k_norm(const float* __restrict__ f1, const float* __restrict__ f2) {
    int g = blockIdx.x * blockDim.x + threadIdx.x;
    if (g < NROWS) g_ln[g] = 0.0f;
    int gw   = g >> 5;
    int lane = threadIdx.x & 31;
    int which = gw >= NROWS;
    int row = which ? gw - NROWS : gw;
    const float* in = which ? f2 : f1;
    float4 v = reinterpret_cast<const float4*>(in)[row * 32 + lane];
    float ss = v.x * v.x + v.y * v.y + v.z * v.z + v.w * v.w;
    #pragma unroll
    for (int off = 16; off > 0; off >>= 1)
        ss += __shfl_xor_sync(0xffffffffu, ss, off);
    float inv = 1.0f / fmaxf(sqrtf(ss), C_EPS);
    float4 o = make_float4(v.x * inv, v.y * inv, v.z * inv, v.w * inv);
    float* outN = which ? g_f2n : g_f1n;
    __half* outH = which ? g_f2h : g_f1h;
    reinterpret_cast<float4*>(outN)[row * 32 + lane] = o;
    __half2 p0 = __floats2half2_rn(o.x, o.y);
    __half2 p1 = __floats2half2_rn(o.z, o.w);
    reinterpret_cast<__half2*>(outH)[row * 64 + lane * 2]     = p0;
    reinterpret_cast<__half2*>(outH)[row * 64 + lane * 2 + 1] = p1;
}

// ---------------- single block: histogram + scan + psum + scatter + scalars ----------------
__global__ void k_scanscatter(const int* __restrict__ labels) {
    __shared__ int   shist[NLAB];
    __shared__ int   scur[NLAB];
    __shared__ int   wsum[32];
    __shared__ float fsum[32];
    int tid = threadIdx.x, lane = tid & 31, w = tid >> 5;
    if (tid == 0) { g_possim = 0.0f; g_lossacc = 0.0f; g_ctr1 = 0; g_ctr2 = 0; }
    shist[tid] = 0;
    __syncthreads();
    int labl[8];
    #pragma unroll
    for (int k = 0; k < 8; ++k) {
        labl[k] = labels[k * NLAB + tid];
        atomicAdd(&shist[labl[k]], 1);
    }
    __syncthreads();
    int h = shist[tid];
    float hh = (float)h * (float)h;

    int v = h;
    #pragma unroll
    for (int off = 1; off < 32; off <<= 1) {
        int u = __shfl_up_sync(0xffffffffu, v, off);
        if (lane >= off) v += u;
    }
    #pragma unroll
    for (int off = 16; off > 0; off >>= 1)
        hh += __shfl_xor_sync(0xffffffffu, hh, off);
    if (lane == 31) wsum[w] = v;
    if (lane == 0)  fsum[w] = hh;
    __syncthreads();
    if (w == 0) {
        int s = wsum[lane];
        #pragma unroll
        for (int off = 1; off < 32; off <<= 1) {
            int u = __shfl_up_sync(0xffffffffu, s, off);
            if (lane >= off) s += u;
        }
        wsum[lane] = s;
        float f = fsum[lane];
        #pragma unroll
        for (int off = 16; off > 0; off >>= 1)
            f += __shfl_xor_sync(0xffffffffu, f, off);
        if (lane == 0) g_psum = f;
    }
    __syncthreads();
    int incl = v + (w > 0 ? wsum[w - 1] : 0);
    g_labOff[tid + 1] = incl;
    if (tid == 0) g_labOff[0] = 0;
    scur[tid] = incl - h;
    __syncthreads();
    #pragma unroll
    for (int k = 0; k < 8; ++k) {
        int i = k * NLAB + tid;
        int p = atomicAdd(&scur[labl[k]], 1);
        g_labRows[p] = i;
    }
}

// ---------------- positive pairs (exact fp32) + fused t (last block) ----------------
__global__ void k_pos(const int* __restrict__ labels) {
    __shared__ float bps[8];
    int row  = (blockIdx.x * blockDim.x + threadIdx.x) >> 5;
    int lane = threadIdx.x & 31;
    int wid  = threadIdx.x >> 5;
    int lab = __ldg(&labels[row]);
    int beg = g_labOff[lab], end = g_labOff[lab + 1];
    float4 a = reinterpret_cast<const float4*>(g_f1n)[row * 32 + lane];

    float possim = 0.0f, fpsum = 0.0f, lpsum = 0.0f;
    for (int p = beg; p < end; ++p) {
        int j = g_labRows[p];
        float4 b = reinterpret_cast<const float4*>(g_f2n)[j * 32 + lane];
        float d = a.x * b.x + a.y * b.y + a.z * b.z + a.w * b.w;
        #pragma unroll
        for (int off = 16; off > 0; off >>= 1)
            d += __shfl_xor_sync(0xffffffffu, d, off);
        float s = fminf(fmaxf(d, -1.0f), 1.0f);
        possim += s;
        float fp;
        if (s > C_THRESHOLD)
            fp = s * C_COSM - sqrtf(fmaxf(1.0f - s * s, 0.0f)) * C_SINM;
        else
            fp = s - C_MM;
        fpsum += fp;
        lpsum += __expf(fp * C_INVT);
    }
    if (lane == 0) {
        int cnt = end - beg;
        g_rt[row] = fpsum / (float)cnt;
        g_lp[row] = lpsum;
        bps[wid] = possim;
    }
    __syncthreads();
    if (threadIdx.x == 0) {
        float ps = 0.0f;
        #pragma unroll
        for (int i = 0; i < 8; ++i) ps += bps[i];
        atomicAdd(&g_possim, ps);
        __threadfence();
        int c = atomicAdd(&g_ctr1, 1);
        if (c == (int)gridDim.x - 1)
            g_t = C_ALPHA * (g_possim / g_psum);
    }
}

// ---------------- fused f16 tensor-core GEMM + logit_neg epilogue ----------------
struct SmemT {
    __half As[128 * STRIDE];
    __half Bs[128 * STRIDE];
    int   labA[128];
    int   labB[128];
    float rtS[128];
    float lnpart[128];
};

__device__ __forceinline__ void ldsm_x4(uint32_t& r0, uint32_t& r1, uint32_t& r2, uint32_t& r3,
                                        uint32_t addr) {
    asm volatile("ldmatrix.sync.aligned.m8n8.x4.shared.b16 {%0,%1,%2,%3}, [%4];\n"
                 : "=r"(r0), "=r"(r1), "=r"(r2), "=r"(r3) : "r"(addr));
}
// f16 x f16 -> f16 accumulate: 2x rate vs f32 accumulate
__device__ __forceinline__ void mma16816h(uint32_t* d, const uint32_t* a, const uint32_t* b) {
    asm volatile("mma.sync.aligned.m16n8k16.row.col.f16.f16.f16.f16 "
                 "{%0,%1}, {%2,%3,%4,%5}, {%6,%7}, {%0,%1};\n"
                 : "+r"(d[0]), "+r"(d[1])
                 : "r"(a[0]), "r"(a[1]), "r"(a[2]), "r"(a[3]), "r"(b[0]), "r"(b[1]));
}

__device__ __forceinline__ float neg_term(float v, int la, int lb, float rt, float t) {
    float s = fminf(fmaxf(v, -1.0f), 1.0f);
    if (la == lb) return 0.0f;                  // positives excluded from logit_neg
    float s3 = (s > rt) ? s * (t + s) : s;      // curricular hard-negative boost
    return ex2_approx(s3 * C_K2);               // exp(s3/T)
}

__global__ __launch_bounds__(256, 2) void k_main(const int* __restrict__ labels) {
    extern __shared__ char smraw[];
    SmemT& sm = *reinterpret_cast<SmemT*>(smraw);
    const int tid = threadIdx.x, lane = tid & 31, wid = tid >> 5;
    const int bx = blockIdx.x, by = blockIdx.y;

    // ---- load 128x128 f16 tiles (full K at once) ----
    const uint4* ga = reinterpret_cast<const uint4*>(g_f1h + (size_t)by * 128 * NC);
    const uint4* gb = reinterpret_cast<const uint4*>(g_f2h + (size_t)bx * 128 * NC);
    #pragma unroll
    for (int it = 0; it < 8; ++it) {
        int r = it * 16 + (tid >> 4);
        int c = tid & 15;                       // 16B chunk = 8 f16
        uint4 va = ga[r * 16 + c];
        uint4 vb = gb[r * 16 + c];
        *reinterpret_cast<uint4*>(sm.As + r * STRIDE + c * 8) = va;
        *reinterpret_cast<uint4*>(sm.Bs + r * STRIDE + c * 8) = vb;
    }
    if (tid < 128) {
        sm.labA[tid] = labels[by * 128 + tid];
        sm.labB[tid] = labels[bx * 128 + tid];
        sm.rtS[tid]  = g_rt[by * 128 + tid];
        sm.lnpart[tid] = 0.0f;
    }
    __syncthreads();

    const int wm = wid >> 2;      // 0..1  -> 64 rows
    const int wn = wid & 3;       // 0..3  -> 32 cols

    uint32_t acc[4][4][2];
    #pragma unroll
    for (int mi = 0; mi < 4; ++mi)
        #pragma unroll
        for (int ni = 0; ni < 4; ++ni) { acc[mi][ni][0] = 0u; acc[mi][ni][1] = 0u; }

    uint32_t aBase = (uint32_t)__cvta_generic_to_shared(sm.As);
    uint32_t bBase = (uint32_t)__cvta_generic_to_shared(sm.Bs);

    #pragma unroll
    for (int k16 = 0; k16 < 8; ++k16) {
        uint32_t af[4][4], bf[4][2];
        #pragma unroll
        for (int mi = 0; mi < 4; ++mi) {
            int row = wm * 64 + mi * 16 + (lane & 15);
            uint32_t addr = aBase + (uint32_t)(row * STRIDE + k16 * 16 + (lane >> 4) * 8) * 2u;
            ldsm_x4(af[mi][0], af[mi][1], af[mi][2], af[mi][3], addr);
        }
        // B: one ldmatrix.x4 covers two n-tiles (ni, ni+1) x two k-halves
        #pragma unroll
        for (int np = 0; np < 2; ++np) {
            int nrow = wn * 32 + (np * 2 + (lane >> 4)) * 8 + (lane & 7);
            uint32_t addr = bBase + (uint32_t)(nrow * STRIDE + k16 * 16 + ((lane >> 3) & 1) * 8) * 2u;
            ldsm_x4(bf[np * 2][0], bf[np * 2][1], bf[np * 2 + 1][0], bf[np * 2 + 1][1], addr);
        }
        #pragma unroll
        for (int mi = 0; mi < 4; ++mi)
            #pragma unroll
            for (int ni = 0; ni < 4; ++ni)
                mma16816h(acc[mi][ni], af[mi], bf[ni]);
    }

    // ---- epilogue: logit_neg accumulation, no sim write-back ----
    const float t = g_t;
    int lbr[8];
    #pragma unroll
    for (int ni = 0; ni < 4; ++ni) {
        int c0 = wn * 32 + ni * 8 + 2 * (lane & 3);
        lbr[2 * ni]     = sm.labB[c0];
        lbr[2 * ni + 1] = sm.labB[c0 + 1];
    }
    #pragma unroll
    for (int mi = 0; mi < 4; ++mi) {
        int rl = wm * 64 + mi * 16 + (lane >> 2);
        int rh = rl + 8;
        float rtl = sm.rtS[rl], rth = sm.rtS[rh];
        int   lal = sm.labA[rl], lah = sm.labA[rh];
        float sl = 0.0f, shi = 0.0f;
        #pragma unroll
        for (int ni = 0; ni < 4; ++ni) {
            float2 lo = __half22float2(*reinterpret_cast<const __half2*>(&acc[mi][ni][0]));
            float2 hi = __half22float2(*reinterpret_cast<const __half2*>(&acc[mi][ni][1]));
            sl  += neg_term(lo.x, lal, lbr[2 * ni],     rtl, t);
            sl  += neg_term(lo.y, lal, lbr[2 * ni + 1], rtl, t);
            shi += neg_term(hi.x, lah, lbr[2 * ni],     rth, t);
            shi += neg_term(hi.y, lah, lbr[2 * ni + 1], rth, t);
        }
        sl  += __shfl_xor_sync(0xffffffffu, sl, 1);
        sl  += __shfl_xor_sync(0xffffffffu, sl, 2);
        shi += __shfl_xor_sync(0xffffffffu, shi, 1);
        shi += __shfl_xor_sync(0xffffffffu, shi, 2);
        if ((lane & 3) == 0) {
            atomicAdd(&sm.lnpart[rl], sl);
            atomicAdd(&sm.lnpart[rh], shi);
        }
    }
    __syncthreads();
    if (tid < 128) atomicAdd(&g_ln[by * 128 + tid], sm.lnpart[tid]);
}

// ---------------- final loss (fused: last block writes output) ----------------
__global__ void k_loss(float* __restrict__ out) {
    int i = blockIdx.x * blockDim.x + threadIdx.x;
    float lp = g_lp[i];
    float v = logf((lp + g_ln[i]) / lp);   // == -log(lp/(ln+lp))
    #pragma unroll
    for (int off = 16; off > 0; off >>= 1)
        v += __shfl_xor_sync(0xffffffffu, v, off);
    __shared__ float ws[8];
    int wid = threadIdx.x >> 5, lane = threadIdx.x & 31;
    if (lane == 0) ws[wid] = v;
    __syncthreads();
    if (threadIdx.x == 0) {
        float s = 0.0f;
        #pragma unroll
        for (int w = 0; w < 8; ++w) s += ws[w];
        atomicAdd(&g_lossacc, s);
        __threadfence();
        int c = atomicAdd(&g_ctr2, 1);
        if (c == (int)gridDim.x - 1)
            out[0] = g_lossacc * (1.0f / (float)NROWS);
    }
}

// ---------------- launch ----------------
extern "C" void kernel_launch(void* const* d_in, const int* in_sizes, int n_in,
                              void* d_out, int out_size) {
    const float* f1 = (const float*)d_in[0];
    const float* f2 = (const float*)d_in[1];
    const int* labels = (const int*)d_in[2];
    float* out = (float*)d_out;

    cudaFuncSetAttribute(k_main, cudaFuncAttributeMaxDynamicSharedMemorySize,
                         (int)sizeof(SmemT));

    k_norm<<<2 * NROWS / 8, 256>>>(f1, f2);
    k_scanscatter<<<1, NLAB>>>(labels);
    k_pos<<<NROWS / 8, 256>>>(labels);

    dim3 grid(NROWS / 128, NROWS / 128);
    k_main<<<grid, 256, sizeof(SmemT)>>>(labels);

    k_loss<<<NROWS / 256, 256>>>(out);
}

// round 17
// speedup vs baseline: 1.5102x; 1.4481x over previous
#include <cuda_runtime.h>
#include <cuda_fp16.h>
#include <cstdint>
#include <cstddef>

// ---------------- problem constants ----------------
#define NROWS 8192
#define NC    128
#define NLAB  1024
#define STRIDE 136   // smem row stride in f16 elements (padding kills ldmatrix conflicts)

// fp32 normalized features (row-major) for exact positive-pair math
__device__ float g_f1n[(size_t)NROWS * NC];
__device__ float g_f2n[(size_t)NROWS * NC];
// f16 normalized features (row-major) for tensor-core GEMM
__device__ __half g_f1h[(size_t)NROWS * NC];
__device__ __half g_f2h[(size_t)NROWS * NC];

__device__ int   g_labOff[NLAB + 1];
__device__ int   g_labRows[NROWS];

__device__ float g_lp[NROWS];      // logit_pos per row (exact fp32)
__device__ float g_ln[NROWS];      // all-pairs exp sum per row (positives subtracted later)
__device__ float g_rt[NROWS];      // row_target
__device__ float g_possim;         // sum of clamped sim over positives
__device__ float g_psum;           // pos.sum() = sum h^2
__device__ float g_t;
__device__ float g_lossacc;
__device__ int   g_ctr1;           // last-block counter for k_pos
__device__ int   g_ctr2;           // last-block counter for k_loss

// hyperparameters
#define C_COSM      0.8775825618903728f
#define C_SINM      0.4794255386042030f
#define C_THRESHOLD (-0.8775825618903728f)
#define C_MM        0.2397127693021015f
#define C_INVT      (1.0f / 0.07f)
#define C_K2        20.6099291555f   // (1/0.07) * log2(e)  -> for ex2.approx
#define C_ALPHA     0.1f
#define C_EPS       1e-12f

// MUFU.EX2 (f32)
__device__ __forceinline__ float ex2_approx(float x) {
    float r;
    asm("ex2.approx.f32 %0, %1;" : "=f"(r) : "f"(x));
    return r;
}
// MUFU.EX2 (f16x2): two exps per instruction
__device__ __forceinline__ __half2 h2ex2(__half2 x) {
    __half2 r;
    asm("ex2.approx.f16x2 %0, %1;"
        : "=r"(*reinterpret_cast<uint32_t*>(&r))
        : "r"(*reinterpret_cast<const uint32_t*>(&x)));
    return r;
}

// ---------------- fused: row-normalize (f1 AND f2) + zero g_ln ----------------
__global__ void k_norm(const float* __restrict__ f1, const float* __restrict__ f2) {
    int g = blockIdx.x * blockDim.x + threadIdx.x;
    if (g < NROWS) g_ln[g] = 0.0f;
    int gw   = g >> 5;
    int lane = threadIdx.x & 31;
    int which = gw >= NROWS;
    int row = which ? gw - NROWS : gw;
    const float* in = which ? f2 : f1;
    float4 v = reinterpret_cast<const float4*>(in)[row * 32 + lane];
    float ss = v.x * v.x + v.y * v.y + v.z * v.z + v.w * v.w;
    #pragma unroll
    for (int off = 16; off > 0; off >>= 1)
        ss += __shfl_xor_sync(0xffffffffu, ss, off);
    float inv = 1.0f / fmaxf(sqrtf(ss), C_EPS);
    float4 o = make_float4(v.x * inv, v.y * inv, v.z * inv, v.w * inv);
    float* outN = which ? g_f2n : g_f1n;
    __half* outH = which ? g_f2h : g_f1h;
    reinterpret_cast<float4*>(outN)[row * 32 + lane] = o;
    __half2 p0 = __floats2half2_rn(o.x, o.y);
    __half2 p1 = __floats2half2_rn(o.z, o.w);
    reinterpret_cast<__half2*>(outH)[row * 64 + lane * 2]     = p0;
    reinterpret_cast<__half2*>(outH)[row * 64 + lane * 2 + 1] = p1;
}

// ---------------- single block: histogram + scan + psum + scatter + scalars ----------------
__global__ void k_scanscatter(const int* __restrict__ labels) {
    __shared__ int   shist[NLAB];
    __shared__ int   scur[NLAB];
    __shared__ int   wsum[32];
    __shared__ float fsum[32];
    int tid = threadIdx.x, lane = tid & 31, w = tid >> 5;
    if (tid == 0) { g_possim = 0.0f; g_lossacc = 0.0f; g_ctr1 = 0; g_ctr2 = 0; }
    shist[tid] = 0;
    __syncthreads();
    int labl[8];
    #pragma unroll
    for (int k = 0; k < 8; ++k) {
        labl[k] = labels[k * NLAB + tid];
        atomicAdd(&shist[labl[k]], 1);
    }
    __syncthreads();
    int h = shist[tid];
    float hh = (float)h * (float)h;

    int v = h;
    #pragma unroll
    for (int off = 1; off < 32; off <<= 1) {
        int u = __shfl_up_sync(0xffffffffu, v, off);
        if (lane >= off) v += u;
    }
    #pragma unroll
    for (int off = 16; off > 0; off >>= 1)
        hh += __shfl_xor_sync(0xffffffffu, hh, off);
    if (lane == 31) wsum[w] = v;
    if (lane == 0)  fsum[w] = hh;
    __syncthreads();
    if (w == 0) {
        int s = wsum[lane];
        #pragma unroll
        for (int off = 1; off < 32; off <<= 1) {
            int u = __shfl_up_sync(0xffffffffu, s, off);
            if (lane >= off) s += u;
        }
        wsum[lane] = s;
        float f = fsum[lane];
        #pragma unroll
        for (int off = 16; off > 0; off >>= 1)
            f += __shfl_xor_sync(0xffffffffu, f, off);
        if (lane == 0) g_psum = f;
    }
    __syncthreads();
    int incl = v + (w > 0 ? wsum[w - 1] : 0);
    g_labOff[tid + 1] = incl;
    if (tid == 0) g_labOff[0] = 0;
    scur[tid] = incl - h;
    __syncthreads();
    #pragma unroll
    for (int k = 0; k < 8; ++k) {
        int i = k * NLAB + tid;
        int p = atomicAdd(&scur[labl[k]], 1);
        g_labRows[p] = i;
    }
}

// ---------------- positive pairs (exact fp32) + fused t (last block) ----------------
__global__ void k_pos(const int* __restrict__ labels) {
    __shared__ float bps[8];
    int row  = (blockIdx.x * blockDim.x + threadIdx.x) >> 5;
    int lane = threadIdx.x & 31;
    int wid  = threadIdx.x >> 5;
    int lab = __ldg(&labels[row]);
    int beg = g_labOff[lab], end = g_labOff[lab + 1];
    float4 a = reinterpret_cast<const float4*>(g_f1n)[row * 32 + lane];

    float possim = 0.0f, fpsum = 0.0f, lpsum = 0.0f;
    for (int p = beg; p < end; ++p) {
        int j = g_labRows[p];
        float4 b = reinterpret_cast<const float4*>(g_f2n)[j * 32 + lane];
        float d = a.x * b.x + a.y * b.y + a.z * b.z + a.w * b.w;
        #pragma unroll
        for (int off = 16; off > 0; off >>= 1)
            d += __shfl_xor_sync(0xffffffffu, d, off);
        float s = fminf(fmaxf(d, -1.0f), 1.0f);
        possim += s;
        float fp;
        if (s > C_THRESHOLD)
            fp = s * C_COSM - sqrtf(fmaxf(1.0f - s * s, 0.0f)) * C_SINM;
        else
            fp = s - C_MM;
        fpsum += fp;
        lpsum += __expf(fp * C_INVT);
    }
    if (lane == 0) {
        int cnt = end - beg;
        g_rt[row] = fpsum / (float)cnt;
        g_lp[row] = lpsum;
        bps[wid] = possim;
    }
    __syncthreads();
    if (threadIdx.x == 0) {
        float ps = 0.0f;
        #pragma unroll
        for (int i = 0; i < 8; ++i) ps += bps[i];
        atomicAdd(&g_possim, ps);
        __threadfence();
        int c = atomicAdd(&g_ctr1, 1);
        if (c == (int)gridDim.x - 1)
            g_t = C_ALPHA * (g_possim / g_psum);
    }
}

// ---------------- fused f16 tensor-core GEMM + all-pairs exp-sum epilogue ----------------
struct SmemT {
    __half As[128 * STRIDE];
    __half Bs[128 * STRIDE];
    float rtS[128];
    float lnpart[128];
};

__device__ __forceinline__ void ldsm_x4(uint32_t& r0, uint32_t& r1, uint32_t& r2, uint32_t& r3,
                                        uint32_t addr) {
    asm volatile("ldmatrix.sync.aligned.m8n8.x4.shared.b16 {%0,%1,%2,%3}, [%4];\n"
                 : "=r"(r0), "=r"(r1), "=r"(r2), "=r"(r3) : "r"(addr));
}
// f16 x f16 -> f16 accumulate: 2x rate vs f32 accumulate
__device__ __forceinline__ void mma16816h(uint32_t* d, const uint32_t* a, const uint32_t* b) {
    asm volatile("mma.sync.aligned.m16n8k16.row.col.f16.f16.f16.f16 "
                 "{%0,%1}, {%2,%3,%4,%5}, {%6,%7}, {%0,%1};\n"
                 : "+r"(d[0]), "+r"(d[1])
                 : "r"(a[0]), "r"(a[1]), "r"(a[2]), "r"(a[3]), "r"(b[0]), "r"(b[1]));
}

#define CP_ASYNC16(dst, src) \
    asm volatile("cp.async.cg.shared.global [%0], [%1], 16;" :: "r"(dst), "l"(src))

// half2 negative-branch term for a pair of columns (no label mask; positives
// are included here and subtracted in k_loss)
__device__ __forceinline__ __half2 neg2(__half2 s, __half2 rt2, __half2 t2, __half2 k2) {
    __half2 boost = __hmul2(s, __hadd2(s, t2));     // s*(t+s)
    __half2 m     = __hgt2(s, rt2);                 // 1.0 / 0.0
    __half2 s3    = __hfma2(m, __hsub2(boost, s), s);
    return h2ex2(__hmul2(s3, k2));                  // exp(s3/T)
}

__global__ __launch_bounds__(256, 3) void k_main() {
    extern __shared__ char smraw[];
    SmemT& sm = *reinterpret_cast<SmemT*>(smraw);
    const int tid = threadIdx.x, lane = tid & 31, wid = tid >> 5;
    const int bx = blockIdx.x, by = blockIdx.y;

    // ---- load 128x128 f16 tiles via cp.async (no RF round-trip) ----
    const char* ga = reinterpret_cast<const char*>(g_f1h + (size_t)by * 128 * NC);
    const char* gb = reinterpret_cast<const char*>(g_f2h + (size_t)bx * 128 * NC);
    uint32_t aB = (uint32_t)__cvta_generic_to_shared(sm.As);
    uint32_t bB = (uint32_t)__cvta_generic_to_shared(sm.Bs);
    #pragma unroll
    for (int it = 0; it < 8; ++it) {
        int r = it * 16 + (tid >> 4);
        int c = tid & 15;                       // 16B chunk = 8 f16
        uint32_t so = (uint32_t)(r * STRIDE + c * 8) * 2u;
        size_t  go = (size_t)(r * 16 + c) * 16u;
        CP_ASYNC16(aB + so, ga + go);
        CP_ASYNC16(bB + so, gb + go);
    }
    asm volatile("cp.async.commit_group;");
    if (tid < 128) {
        sm.rtS[tid]    = g_rt[by * 128 + tid];
        sm.lnpart[tid] = 0.0f;
    }
    asm volatile("cp.async.wait_group 0;");
    __syncthreads();

    const int wm = wid >> 2;      // 0..1  -> 64 rows
    const int wn = wid & 3;       // 0..3  -> 32 cols

    uint32_t acc[4][4][2];
    #pragma unroll
    for (int mi = 0; mi < 4; ++mi)
        #pragma unroll
        for (int ni = 0; ni < 4; ++ni) { acc[mi][ni][0] = 0u; acc[mi][ni][1] = 0u; }

    #pragma unroll
    for (int k16 = 0; k16 < 8; ++k16) {
        uint32_t af[4][4], bf[4][2];
        #pragma unroll
        for (int mi = 0; mi < 4; ++mi) {
            int row = wm * 64 + mi * 16 + (lane & 15);
            uint32_t addr = aB + (uint32_t)(row * STRIDE + k16 * 16 + (lane >> 4) * 8) * 2u;
            ldsm_x4(af[mi][0], af[mi][1], af[mi][2], af[mi][3], addr);
        }
        #pragma unroll
        for (int np = 0; np < 2; ++np) {
            int nrow = wn * 32 + (np * 2 + (lane >> 4)) * 8 + (lane & 7);
            uint32_t addr = bB + (uint32_t)(nrow * STRIDE + k16 * 16 + ((lane >> 3) & 1) * 8) * 2u;
            ldsm_x4(bf[np * 2][0], bf[np * 2][1], bf[np * 2 + 1][0], bf[np * 2 + 1][1], addr);
        }
        #pragma unroll
        for (int mi = 0; mi < 4; ++mi)
            #pragma unroll
            for (int ni = 0; ni < 4; ++ni)
                mma16816h(acc[mi][ni], af[mi], bf[ni]);
    }

    // ---- epilogue: half2 SIMD, no label masking ----
    const __half2 t2 = __float2half2_rn(g_t);
    const __half2 k2 = __float2half2_rn(C_K2);
    #pragma unroll
    for (int mi = 0; mi < 4; ++mi) {
        int rl = wm * 64 + mi * 16 + (lane >> 2);
        int rh = rl + 8;
        __half2 rt2l = __float2half2_rn(sm.rtS[rl]);
        __half2 rt2h = __float2half2_rn(sm.rtS[rh]);
        __half2 al = __float2half2_rn(0.0f), ah = __float2half2_rn(0.0f);
        #pragma unroll
        for (int ni = 0; ni < 4; ++ni) {
            __half2 lo = *reinterpret_cast<const __half2*>(&acc[mi][ni][0]);
            __half2 hi = *reinterpret_cast<const __half2*>(&acc[mi][ni][1]);
            al = __hadd2(al, neg2(lo, rt2l, t2, k2));
            ah = __hadd2(ah, neg2(hi, rt2h, t2, k2));
        }
        float2 fl = __half22float2(al);
        float2 fh = __half22float2(ah);
        float sl = fl.x + fl.y, shi = fh.x + fh.y;
        sl  += __shfl_xor_sync(0xffffffffu, sl, 1);
        sl  += __shfl_xor_sync(0xffffffffu, sl, 2);
        shi += __shfl_xor_sync(0xffffffffu, shi, 1);
        shi += __shfl_xor_sync(0xffffffffu, shi, 2);
        if ((lane & 3) == 0) {
            atomicAdd(&sm.lnpart[rl], sl);
            atomicAdd(&sm.lnpart[rh], shi);
        }
    }
    __syncthreads();
    if (tid < 128) atomicAdd(&g_ln[by * 128 + tid], sm.lnpart[tid]);
}

// ---------------- final loss: warp per row, subtract positive terms ----------------
__global__ void k_loss(const int* __restrict__ labels, float* __restrict__ out) {
    int row  = (blockIdx.x * blockDim.x + threadIdx.x) >> 5;
    int lane = threadIdx.x & 31;
    int wid  = threadIdx.x >> 5;
    int lab = __ldg(&labels[row]);
    int beg = g_labOff[lab], end = g_labOff[lab + 1];
    float4 a = reinterpret_cast<const float4*>(g_f1n)[row * 32 + lane];
    const float rt = g_rt[row], t = g_t;

    // recompute positive sims (fp32 ~ f16 GEMM values) and subtract their
    // negative-branch contribution from the all-pairs sum
    float corr = 0.0f;
    for (int p = beg; p < end; ++p) {
        int j = g_labRows[p];
        float4 b = reinterpret_cast<const float4*>(g_f2n)[j * 32 + lane];
        float d = a.x * b.x + a.y * b.y + a.z * b.z + a.w * b.w;
        #pragma unroll
        for (int off = 16; off > 0; off >>= 1)
            d += __shfl_xor_sync(0xffffffffu, d, off);
        float s3 = (d > rt) ? d * (t + d) : d;
        corr += ex2_approx(s3 * C_K2);
    }

    __shared__ float ws[8];
    if (lane == 0) {
        float lp = g_lp[row];
        float ln = g_ln[row] - corr;
        ws[wid] = logf((lp + ln) / lp);   // == -log(lp/(ln+lp))
    }
    __syncthreads();
    if (threadIdx.x == 0) {
        float s = 0.0f;
        #pragma unroll
        for (int w = 0; w < 8; ++w) s += ws[w];
        atomicAdd(&g_lossacc, s);
        __threadfence();
        int c = atomicAdd(&g_ctr2, 1);
        if (c == (int)gridDim.x - 1)
            out[0] = g_lossacc * (1.0f / (float)NROWS);
    }
}

// ---------------- launch ----------------
extern "C" void kernel_launch(void* const* d_in, const int* in_sizes, int n_in,
                              void* d_out, int out_size) {
    const float* f1 = (const float*)d_in[0];
    const float* f2 = (const float*)d_in[1];
    const int* labels = (const int*)d_in[2];
    float* out = (float*)d_out;

    cudaFuncSetAttribute(k_main, cudaFuncAttributeMaxDynamicSharedMemorySize,
                         (int)sizeof(SmemT));

    k_norm<<<2 * NROWS / 8, 256>>>(f1, f2);
    k_scanscatter<<<1, NLAB>>>(labels);
    k_pos<<<NROWS / 8, 256>>>(labels);

    dim3 grid(NROWS / 128, NROWS / 128);
    k_main<<<grid, 256, sizeof(SmemT)>>>();

    k_loss<<<NROWS / 8, 256>>>(labels, out);
}